// round 9
// baseline (speedup 1.0000x reference)
#include <cuda_runtime.h>

#define NN 4096
#define HH 64
#define HIK 8
#define NSPLIT 32            // number of j-chunks
#define CHUNK 128            // j's per chunk (two 64-bit mask passes)
#define ITILE 256            // i-rows per force block (128 thr x 2)
#define NIB (NN / ITILE)     // 16 i-ranges
#define NFORCE (NSPLIT * NIB)        // 512 force blocks
#define NMLP ((NN * 16) / 128)       // 512 mlp blocks (16 threads/particle)
#define TBLB 128                     // per-block table bins over [0, 0.5]
#define EPSF 1e-8f

// Deterministic partial-force scratch: [NSPLIT][NN][3]
__device__ float g_partial[NSPLIT * NN * 3];

// fast tanh via exp: abs error ~1e-7..1e-6, no branches
__device__ __forceinline__ float fast_tanh(float x) {
    x = fminf(fmaxf(x, -15.0f), 15.0f);
    float u = __expf(2.0f * x);
    return __fdividef(u - 1.0f, u + 1.0f);
}

// dU(r) = sum_k Wi1[k]*Wi2[k]*(1 - tanh(r*Wi1[k]+bi1[k])^2)
__device__ __forceinline__ float dU_at(float r, const float* wi1,
                                       const float* bb, const float* cc) {
    float d = 0.f;
#pragma unroll
    for (int k = 0; k < HIK; ++k) {
        float th = fast_tanh(fmaf(r, wi1[k], bb[k]));
        d = fmaf(fmaf(-th, th, 1.0f), cc[k], d);
    }
    return d;
}

// ---------------------------------------------------------------------------
// Launch 1: force + MLP in one grid, NO cross-block dependencies.
//   Blocks [0, NFORCE): pairwise force tile (i-range x 128-j chunk).
//   Blocks [NFORCE, ...): MLP, 16 threads/particle.
// ---------------------------------------------------------------------------
__global__ void main_kernel(const float* __restrict__ t,
                            const float* __restrict__ z,
                            const float* __restrict__ lnw,
                            const float* __restrict__ W1,
                            const float* __restrict__ b1,
                            const float* __restrict__ Wv,
                            const float* __restrict__ bv,
                            const float* __restrict__ Wg,
                            const float* __restrict__ bg,
                            const float* __restrict__ Wi1,
                            const float* __restrict__ bi1,
                            const float* __restrict__ Wi2,
                            float* __restrict__ out) {
    int bx = blockIdx.x;
    int tid = threadIdx.x;

    if (bx < NFORCE) {
        // ------------------------- force role -------------------------
        __shared__ float4 zsh[CHUNK];       // (x, y, z, |z|^2)
        __shared__ float  wsh[CHUNK];       // exp(lnw_j)
        __shared__ float  val[TBLB + 1];    // dU at bin edges over [0, 0.5]

        int s  = bx >> 4;    // j-chunk  0..31
        int ib = bx & 15;    // i-range  0..15

        // interaction params (broadcast loads)
        float wi1[HIK], bb[HIK], cc[HIK];
#pragma unroll
        for (int k = 0; k < HIK; ++k) {
            wi1[k] = __ldg(&Wi1[k]);
            bb[k]  = __ldg(&bi1[k]);
            cc[k]  = wi1[k] * __ldg(&Wi2[k]);
        }
        // per-block dU table: 1 bin per thread (+ last edge by thread 0)
        {
            const float h = 0.5f / (float)TBLB;
            val[tid] = dU_at((float)tid * h, wi1, bb, cc);
            if (tid == 0) val[TBLB] = dU_at(0.5f, wi1, bb, cc);
        }
        {
            int jg = s * CHUNK + tid;       // 128 threads stage 128 j's
            float x = z[jg * 3 + 0];
            float y = z[jg * 3 + 1];
            float w = z[jg * 3 + 2];
            zsh[tid] = make_float4(x, y, w, x * x + y * y + w * w);
            wsh[tid] = expf(lnw[jg]);
        }
        __syncthreads();

        int i0 = ib * ITILE + tid;
        int i1 = i0 + 128;

        float zx0 = z[i0 * 3 + 0], zy0 = z[i0 * 3 + 1], zz0 = z[i0 * 3 + 2];
        float zx1 = z[i1 * 3 + 0], zy1 = z[i1 * 3 + 1], zz1 = z[i1 * 3 + 2];

        float ax0 = -2.0f * zx0, ay0 = -2.0f * zy0, az0 = -2.0f * zz0;
        float ax1 = -2.0f * zx1, ay1 = -2.0f * zy1, az1 = -2.0f * zz1;
        float thr0 = 0.25f + 1e-4f - (zx0 * zx0 + zy0 * zy0 + zz0 * zz0);
        float thr1 = 0.25f + 1e-4f - (zx1 * zx1 + zy1 * zy1 + zz1 * zz1);

        float fx0 = 0.f, fy0 = 0.f, fz0 = 0.f;
        float fx1 = 0.f, fy1 = 0.f, fz1 = 0.f;

#pragma unroll 1
        for (int jb = 0; jb < 2; ++jb) {    // two 64-j halves
            const float4* zhalf = &zsh[jb * 64];

            // ---- cheap prefilter: 2x32-bit masks per i-row ----
            unsigned int m0a = 0u, m0b = 0u, m1a = 0u, m1b = 0u;
#pragma unroll
            for (int jj = 0; jj < 32; ++jj) {
                float4 zja = zhalf[jj];
                float4 zjb = zhalf[jj + 32];
                float d0a = fmaf(az0, zja.z, zja.w);
                d0a = fmaf(ay0, zja.y, d0a);
                d0a = fmaf(ax0, zja.x, d0a);
                float d1a = fmaf(az1, zja.z, zja.w);
                d1a = fmaf(ay1, zja.y, d1a);
                d1a = fmaf(ax1, zja.x, d1a);
                float d0b = fmaf(az0, zjb.z, zjb.w);
                d0b = fmaf(ay0, zjb.y, d0b);
                d0b = fmaf(ax0, zjb.x, d0b);
                float d1b = fmaf(az1, zjb.z, zjb.w);
                d1b = fmaf(ay1, zjb.y, d1b);
                d1b = fmaf(ax1, zjb.x, d1b);
                if (d0a < thr0) m0a |= (1u << jj);
                if (d1a < thr1) m1a |= (1u << jj);
                if (d0b < thr0) m0b |= (1u << jj);
                if (d1b < thr1) m1b |= (1u << jj);
            }
            // remove self-pairs (i inside this 64-j half of chunk s)
            if ((i0 >> 7) == s && ((i0 >> 6) & 1) == jb) {
                int r = i0 & 63;
                if (r < 32) m0a &= ~(1u << r); else m0b &= ~(1u << (r - 32));
            }
            if ((i1 >> 7) == s && ((i1 >> 6) & 1) == jb) {
                int r = i1 & 63;
                if (r < 32) m1a &= ~(1u << r); else m1b &= ~(1u << (r - 32));
            }

            unsigned long long m0 = ((unsigned long long)m0b << 32) | m0a;
            unsigned long long m1 = ((unsigned long long)m1b << 32) | m1a;

            // ---- survivors, i-row 0 ----
            while (m0) {
                int b = __ffsll((long long)m0) - 1;
                m0 &= (m0 - 1);
                float4 zj = zhalf[b];
                float dx = zx0 - zj.x;
                float dy = zy0 - zj.y;
                float dz = zz0 - zj.z;
                float d2 = fmaf(dx, dx, EPSF);      // exact (reference) form
                d2 = fmaf(dy, dy, d2);
                d2 = fmaf(dz, dz, d2);
                float rd = rsqrtf(d2);
                float r  = d2 * rd;                 // sqrt(d2)
                float u  = r * (float)(2 * TBLB);   // bin width 0.5/128
                int  iu  = (int)u;
                iu = (iu < TBLB) ? iu : (TBLB - 1);
                float fr = u - (float)iu;
                float e0 = val[iu], e1 = val[iu + 1];
                float dU = fmaf(fr, e1 - e0, e0);
                float coeff = dU * wsh[jb * 64 + b] * rd * (-1.0f / 16.0f);
                coeff = (d2 < 0.25f) ? coeff : 0.0f;   // exact mask decision
                fx0 = fmaf(coeff, dx, fx0);
                fy0 = fmaf(coeff, dy, fy0);
                fz0 = fmaf(coeff, dz, fz0);
            }

            // ---- survivors, i-row 1 ----
            while (m1) {
                int b = __ffsll((long long)m1) - 1;
                m1 &= (m1 - 1);
                float4 zj = zhalf[b];
                float dx = zx1 - zj.x;
                float dy = zy1 - zj.y;
                float dz = zz1 - zj.z;
                float d2 = fmaf(dx, dx, EPSF);
                d2 = fmaf(dy, dy, d2);
                d2 = fmaf(dz, dz, d2);
                float rd = rsqrtf(d2);
                float r  = d2 * rd;
                float u  = r * (float)(2 * TBLB);
                int  iu  = (int)u;
                iu = (iu < TBLB) ? iu : (TBLB - 1);
                float fr = u - (float)iu;
                float e0 = val[iu], e1 = val[iu + 1];
                float dU = fmaf(fr, e1 - e0, e0);
                float coeff = dU * wsh[jb * 64 + b] * rd * (-1.0f / 16.0f);
                coeff = (d2 < 0.25f) ? coeff : 0.0f;
                fx1 = fmaf(coeff, dx, fx1);
                fy1 = fmaf(coeff, dy, fy1);
                fz1 = fmaf(coeff, dz, fz1);
            }
        }

        float* p0 = &g_partial[((size_t)s * NN + (size_t)i0) * 3];
        p0[0] = fx0; p0[1] = fy0; p0[2] = fz0;
        float* p1 = &g_partial[((size_t)s * NN + (size_t)i1) * 3];
        p1[0] = fx1; p1[1] = fy1; p1[2] = fz1;
    } else {
        // -------------------------- mlp role --------------------------
        __shared__ float sW1[4 * HH];   // (D+1, H) row-major
        __shared__ float sWv[HH * 3];
        __shared__ float sWg[HH];
        __shared__ float sb1[HH];

        int mb = bx - NFORCE;
        for (int k = tid; k < 4 * HH; k += 128) sW1[k] = W1[k];
        for (int k = tid; k < HH * 3; k += 128) sWv[k] = Wv[k];
        if (tid < HH) { sWg[tid] = Wg[tid]; sb1[tid] = b1[tid]; }
        __syncthreads();

        int idx = mb * 128 + tid;   // 16 * NN threads total
        int i = idx >> 4;           // particle
        int q = idx & 15;           // 4 hidden units each

        float z0 = z[i * 3 + 0];
        float z1 = z[i * 3 + 1];
        float z2 = z[i * 3 + 2];
        float tv = t[0];

        float v0 = 0.f, v1 = 0.f, v2 = 0.f, g = 0.f;
        int k0 = q * 4;
#pragma unroll
        for (int kk = 0; kk < 4; ++kk) {
            int k = k0 + kk;
            float a = fmaf(z0, sW1[k],
                      fmaf(z1, sW1[HH + k],
                      fmaf(z2, sW1[2 * HH + k],
                      fmaf(tv, sW1[3 * HH + k], sb1[k]))));
            float hh = fast_tanh(a);
            v0 = fmaf(hh, sWv[k * 3 + 0], v0);
            v1 = fmaf(hh, sWv[k * 3 + 1], v1);
            v2 = fmaf(hh, sWv[k * 3 + 2], v2);
            g  = fmaf(hh, sWg[k], g);
        }

#pragma unroll
        for (int off = 1; off < 16; off <<= 1) {
            v0 += __shfl_xor_sync(0xFFFFFFFFu, v0, off);
            v1 += __shfl_xor_sync(0xFFFFFFFFu, v1, off);
            v2 += __shfl_xor_sync(0xFFFFFFFFu, v2, off);
            g  += __shfl_xor_sync(0xFFFFFFFFu, g,  off);
        }

        if (q == 0) {
            v0 += bv[0]; v1 += bv[1]; v2 += bv[2];
            g  += bg[0];
            out[i * 3 + 0] = v0;
            out[i * 3 + 1] = v1;
            out[i * 3 + 2] = v2;
            out[3 * NN + i] = g;
            float w = expf(lnw[i]);
            out[4 * NN + i] = (v0 * v0 + v1 * v1 + v2 * v2 + g * g) * w;
        }
    }
}

// ---------------------------------------------------------------------------
// Launch 2: deterministic reduction.  4 threads per output element, each
// sums 8 partials in fixed ascending s-order (full ILP), then a 2-step
// shfl_xor combine (IEEE add is commutative -> value is deterministic).
// 49K threads total: latency-hiding fixed vs R8's 12K x 64-chain version.
// ---------------------------------------------------------------------------
__global__ void reduce_kernel(float* __restrict__ out) {
    int tid = threadIdx.x;                    // 256
    int idx = blockIdx.x * 64 + (tid >> 2);   // output element < NN*3
    int q   = tid & 3;                        // s-group

    const float* base = &g_partial[(q * 8) * (NN * 3) + idx];
    float a0 = base[0 * (NN * 3)];
    float a1 = base[1 * (NN * 3)];
    float a2 = base[2 * (NN * 3)];
    float a3 = base[3 * (NN * 3)];
    float a4 = base[4 * (NN * 3)];
    float a5 = base[5 * (NN * 3)];
    float a6 = base[6 * (NN * 3)];
    float a7 = base[7 * (NN * 3)];
    float v = ((a0 + a1) + (a2 + a3)) + ((a4 + a5) + (a6 + a7));

    v += __shfl_xor_sync(0xFFFFFFFFu, v, 1);
    v += __shfl_xor_sync(0xFFFFFFFFu, v, 2);

    if (q == 0) out[idx] += v;
}

extern "C" void kernel_launch(void* const* d_in, const int* in_sizes, int n_in,
                              void* d_out, int out_size) {
    (void)in_sizes; (void)n_in; (void)out_size;
    const float* t   = (const float*)d_in[0];
    const float* z   = (const float*)d_in[1];
    const float* lnw = (const float*)d_in[2];
    const float* W1  = (const float*)d_in[3];
    const float* b1  = (const float*)d_in[4];
    const float* Wv  = (const float*)d_in[5];
    const float* bv  = (const float*)d_in[6];
    const float* Wg  = (const float*)d_in[7];
    const float* bg  = (const float*)d_in[8];
    const float* Wi1 = (const float*)d_in[9];
    const float* bi1 = (const float*)d_in[10];
    const float* Wi2 = (const float*)d_in[11];
    // d_in[12] = bi2: only shifts U, not dU/dr -> unused
    float* out = (float*)d_out;

    main_kernel<<<NFORCE + NMLP, 128>>>(t, z, lnw, W1, b1, Wv, bv, Wg, bg,
                                        Wi1, bi1, Wi2, out);
    reduce_kernel<<<(NN * 3) / 64, 256>>>(out);
}

// round 10
// speedup vs baseline: 1.1111x; 1.1111x over previous
#include <cuda_runtime.h>

#define NN 4096
#define HH 64
#define HIK 8
#define NSPLIT 64            // number of j-chunks
#define CHUNK 64             // j's per chunk
#define ITILE 256            // i-rows per force block (128 thr x 2)
#define NIB (NN / ITILE)     // 16 i-ranges
#define NFORCE (NSPLIT * NIB)        // 1024 force blocks
#define NMLP ((NN * 16) / 128)       // 512 mlp blocks (16 threads/particle)
#define TBLB 128                     // per-block table bins over [0, 0.5]
#define EPSF 1e-8f

// Deterministic partial-force scratch: [NSPLIT][NN][3]
__device__ float g_partial[NSPLIT * NN * 3];

// fast tanh via exp: abs error ~1e-7..1e-6, no branches
__device__ __forceinline__ float fast_tanh(float x) {
    x = fminf(fmaxf(x, -15.0f), 15.0f);
    float u = __expf(2.0f * x);
    return __fdividef(u - 1.0f, u + 1.0f);
}

// dU(r) = sum_k Wi1[k]*Wi2[k]*(1 - tanh(r*Wi1[k]+bi1[k])^2)
__device__ __forceinline__ float dU_at(float r, const float* wi1,
                                       const float* bb, const float* cc) {
    float d = 0.f;
#pragma unroll
    for (int k = 0; k < HIK; ++k) {
        float th = fast_tanh(fmaf(r, wi1[k], bb[k]));
        d = fmaf(fmaf(-th, th, 1.0f), cc[k], d);
    }
    return d;
}

// ---------------------------------------------------------------------------
// Launch 1: force + MLP in one grid, NO cross-block dependencies.
// (Identical to the R8 best-known main_kernel.)
// ---------------------------------------------------------------------------
__global__ void main_kernel(const float* __restrict__ t,
                            const float* __restrict__ z,
                            const float* __restrict__ lnw,
                            const float* __restrict__ W1,
                            const float* __restrict__ b1,
                            const float* __restrict__ Wv,
                            const float* __restrict__ bv,
                            const float* __restrict__ Wg,
                            const float* __restrict__ bg,
                            const float* __restrict__ Wi1,
                            const float* __restrict__ bi1,
                            const float* __restrict__ Wi2,
                            float* __restrict__ out) {
    int bx = blockIdx.x;
    int tid = threadIdx.x;

    if (bx < NFORCE) {
        // ------------------------- force role -------------------------
        __shared__ float4 zsh[CHUNK];       // (x, y, z, |z|^2)
        __shared__ float  wsh[CHUNK];       // exp(lnw_j)
        __shared__ float  val[TBLB + 1];    // dU at bin edges over [0, 0.5]

        int s  = bx >> 4;    // j-chunk  0..63
        int ib = bx & 15;    // i-range  0..15

        float wi1[HIK], bb[HIK], cc[HIK];
#pragma unroll
        for (int k = 0; k < HIK; ++k) {
            wi1[k] = __ldg(&Wi1[k]);
            bb[k]  = __ldg(&bi1[k]);
            cc[k]  = wi1[k] * __ldg(&Wi2[k]);
        }
        {
            const float h = 0.5f / (float)TBLB;
            val[tid] = dU_at((float)tid * h, wi1, bb, cc);
            if (tid == 0) val[TBLB] = dU_at(0.5f, wi1, bb, cc);
        }
        if (tid < CHUNK) {
            int jg = s * CHUNK + tid;
            float x = z[jg * 3 + 0];
            float y = z[jg * 3 + 1];
            float w = z[jg * 3 + 2];
            zsh[tid] = make_float4(x, y, w, x * x + y * y + w * w);
            wsh[tid] = expf(lnw[jg]);
        }
        __syncthreads();

        int i0 = ib * ITILE + tid;
        int i1 = i0 + 128;

        float zx0 = z[i0 * 3 + 0], zy0 = z[i0 * 3 + 1], zz0 = z[i0 * 3 + 2];
        float zx1 = z[i1 * 3 + 0], zy1 = z[i1 * 3 + 1], zz1 = z[i1 * 3 + 2];

        float ax0 = -2.0f * zx0, ay0 = -2.0f * zy0, az0 = -2.0f * zz0;
        float ax1 = -2.0f * zx1, ay1 = -2.0f * zy1, az1 = -2.0f * zz1;
        float thr0 = 0.25f + 1e-4f - (zx0 * zx0 + zy0 * zy0 + zz0 * zz0);
        float thr1 = 0.25f + 1e-4f - (zx1 * zx1 + zy1 * zy1 + zz1 * zz1);

        // ---- cheap prefilter: 2x32-bit masks per i-row ----
        unsigned int m0a = 0u, m0b = 0u, m1a = 0u, m1b = 0u;
#pragma unroll
        for (int jj = 0; jj < 32; ++jj) {
            float4 zja = zsh[jj];
            float4 zjb = zsh[jj + 32];
            float d0a = fmaf(az0, zja.z, zja.w);
            d0a = fmaf(ay0, zja.y, d0a);
            d0a = fmaf(ax0, zja.x, d0a);
            float d1a = fmaf(az1, zja.z, zja.w);
            d1a = fmaf(ay1, zja.y, d1a);
            d1a = fmaf(ax1, zja.x, d1a);
            float d0b = fmaf(az0, zjb.z, zjb.w);
            d0b = fmaf(ay0, zjb.y, d0b);
            d0b = fmaf(ax0, zjb.x, d0b);
            float d1b = fmaf(az1, zjb.z, zjb.w);
            d1b = fmaf(ay1, zjb.y, d1b);
            d1b = fmaf(ax1, zjb.x, d1b);
            if (d0a < thr0) m0a |= (1u << jj);
            if (d1a < thr1) m1a |= (1u << jj);
            if (d0b < thr0) m0b |= (1u << jj);
            if (d1b < thr1) m1b |= (1u << jj);
        }
        // remove self-pairs (i inside this j-chunk)
        if ((i0 >> 6) == s) {
            int r = i0 & 63;
            if (r < 32) m0a &= ~(1u << r); else m0b &= ~(1u << (r - 32));
        }
        if ((i1 >> 6) == s) {
            int r = i1 & 63;
            if (r < 32) m1a &= ~(1u << r); else m1b &= ~(1u << (r - 32));
        }

        unsigned long long m0 = ((unsigned long long)m0b << 32) | m0a;
        unsigned long long m1 = ((unsigned long long)m1b << 32) | m1a;

        // ---- survivors, i-row 0 ----
        float fx0 = 0.f, fy0 = 0.f, fz0 = 0.f;
        while (m0) {
            int b = __ffsll((long long)m0) - 1;
            m0 &= (m0 - 1);
            float4 zj = zsh[b];
            float dx = zx0 - zj.x;
            float dy = zy0 - zj.y;
            float dz = zz0 - zj.z;
            float d2 = fmaf(dx, dx, EPSF);      // exact (reference) form
            d2 = fmaf(dy, dy, d2);
            d2 = fmaf(dz, dz, d2);
            float rd = rsqrtf(d2);
            float r  = d2 * rd;                 // sqrt(d2)
            float u  = r * (float)(2 * TBLB);   // bin width 0.5/128
            int  iu  = (int)u;
            iu = (iu < TBLB) ? iu : (TBLB - 1);
            float fr = u - (float)iu;
            float e0 = val[iu], e1 = val[iu + 1];
            float dU = fmaf(fr, e1 - e0, e0);
            float coeff = dU * wsh[b] * rd * (-1.0f / 16.0f);
            coeff = (d2 < 0.25f) ? coeff : 0.0f;   // exact mask decision
            fx0 = fmaf(coeff, dx, fx0);
            fy0 = fmaf(coeff, dy, fy0);
            fz0 = fmaf(coeff, dz, fz0);
        }

        // ---- survivors, i-row 1 ----
        float fx1 = 0.f, fy1 = 0.f, fz1 = 0.f;
        while (m1) {
            int b = __ffsll((long long)m1) - 1;
            m1 &= (m1 - 1);
            float4 zj = zsh[b];
            float dx = zx1 - zj.x;
            float dy = zy1 - zj.y;
            float dz = zz1 - zj.z;
            float d2 = fmaf(dx, dx, EPSF);
            d2 = fmaf(dy, dy, d2);
            d2 = fmaf(dz, dz, d2);
            float rd = rsqrtf(d2);
            float r  = d2 * rd;
            float u  = r * (float)(2 * TBLB);
            int  iu  = (int)u;
            iu = (iu < TBLB) ? iu : (TBLB - 1);
            float fr = u - (float)iu;
            float e0 = val[iu], e1 = val[iu + 1];
            float dU = fmaf(fr, e1 - e0, e0);
            float coeff = dU * wsh[b] * rd * (-1.0f / 16.0f);
            coeff = (d2 < 0.25f) ? coeff : 0.0f;
            fx1 = fmaf(coeff, dx, fx1);
            fy1 = fmaf(coeff, dy, fy1);
            fz1 = fmaf(coeff, dz, fz1);
        }

        float* p0 = &g_partial[((size_t)s * NN + (size_t)i0) * 3];
        p0[0] = fx0; p0[1] = fy0; p0[2] = fz0;
        float* p1 = &g_partial[((size_t)s * NN + (size_t)i1) * 3];
        p1[0] = fx1; p1[1] = fy1; p1[2] = fz1;
    } else {
        // -------------------------- mlp role --------------------------
        __shared__ float sW1[4 * HH];   // (D+1, H) row-major
        __shared__ float sWv[HH * 3];
        __shared__ float sWg[HH];
        __shared__ float sb1[HH];

        int mb = bx - NFORCE;
        for (int k = tid; k < 4 * HH; k += 128) sW1[k] = W1[k];
        for (int k = tid; k < HH * 3; k += 128) sWv[k] = Wv[k];
        if (tid < HH) { sWg[tid] = Wg[tid]; sb1[tid] = b1[tid]; }
        __syncthreads();

        int idx = mb * 128 + tid;   // 16 * NN threads total
        int i = idx >> 4;           // particle
        int q = idx & 15;           // 4 hidden units each

        float z0 = z[i * 3 + 0];
        float z1 = z[i * 3 + 1];
        float z2 = z[i * 3 + 2];
        float tv = t[0];

        float v0 = 0.f, v1 = 0.f, v2 = 0.f, g = 0.f;
        int k0 = q * 4;
#pragma unroll
        for (int kk = 0; kk < 4; ++kk) {
            int k = k0 + kk;
            float a = fmaf(z0, sW1[k],
                      fmaf(z1, sW1[HH + k],
                      fmaf(z2, sW1[2 * HH + k],
                      fmaf(tv, sW1[3 * HH + k], sb1[k]))));
            float hh = fast_tanh(a);
            v0 = fmaf(hh, sWv[k * 3 + 0], v0);
            v1 = fmaf(hh, sWv[k * 3 + 1], v1);
            v2 = fmaf(hh, sWv[k * 3 + 2], v2);
            g  = fmaf(hh, sWg[k], g);
        }

#pragma unroll
        for (int off = 1; off < 16; off <<= 1) {
            v0 += __shfl_xor_sync(0xFFFFFFFFu, v0, off);
            v1 += __shfl_xor_sync(0xFFFFFFFFu, v1, off);
            v2 += __shfl_xor_sync(0xFFFFFFFFu, v2, off);
            g  += __shfl_xor_sync(0xFFFFFFFFu, g,  off);
        }

        if (q == 0) {
            v0 += bv[0]; v1 += bv[1]; v2 += bv[2];
            g  += bg[0];
            out[i * 3 + 0] = v0;
            out[i * 3 + 1] = v1;
            out[i * 3 + 2] = v2;
            out[3 * NN + i] = g;
            float w = expf(lnw[i]);
            out[4 * NN + i] = (v0 * v0 + v1 * v1 + v2 * v2 + g * g) * w;
        }
    }
}

// ---------------------------------------------------------------------------
// Launch 2: deterministic reduction, warp-coalesced.
//   Block = 256 threads = 8 warps, covering 32 output elements.
//   Warp w owns s-slices [8w, 8w+8): each lane loads 8 partials for its
//   element -> every LDG is a fully-coalesced 128B line, 8 independent
//   loads in flight per thread.  Per-warp sums go to smem; warp 0 combines
//   the 8 warp-partials in FIXED ascending order -> bit-deterministic.
//   384 blocks x 8 warps saturate memory parallelism.
// ---------------------------------------------------------------------------
__global__ void reduce_kernel(float* __restrict__ out) {
    __shared__ float acc[8][32];

    int tid  = threadIdx.x;
    int w    = tid >> 5;                   // warp 0..7 -> s-group
    int lane = tid & 31;
    int idx  = blockIdx.x * 32 + lane;     // output element < NN*3

    const float* base = &g_partial[(w * 8) * (NN * 3) + idx];
    float a0 = base[0 * (NN * 3)];
    float a1 = base[1 * (NN * 3)];
    float a2 = base[2 * (NN * 3)];
    float a3 = base[3 * (NN * 3)];
    float a4 = base[4 * (NN * 3)];
    float a5 = base[5 * (NN * 3)];
    float a6 = base[6 * (NN * 3)];
    float a7 = base[7 * (NN * 3)];
    acc[w][lane] = ((a0 + a1) + (a2 + a3)) + ((a4 + a5) + (a6 + a7));
    __syncthreads();

    if (w == 0) {
        float v = ((acc[0][lane] + acc[1][lane]) + (acc[2][lane] + acc[3][lane]))
                + ((acc[4][lane] + acc[5][lane]) + (acc[6][lane] + acc[7][lane]));
        out[idx] += v;
    }
}

extern "C" void kernel_launch(void* const* d_in, const int* in_sizes, int n_in,
                              void* d_out, int out_size) {
    (void)in_sizes; (void)n_in; (void)out_size;
    const float* t   = (const float*)d_in[0];
    const float* z   = (const float*)d_in[1];
    const float* lnw = (const float*)d_in[2];
    const float* W1  = (const float*)d_in[3];
    const float* b1  = (const float*)d_in[4];
    const float* Wv  = (const float*)d_in[5];
    const float* bv  = (const float*)d_in[6];
    const float* Wg  = (const float*)d_in[7];
    const float* bg  = (const float*)d_in[8];
    const float* Wi1 = (const float*)d_in[9];
    const float* bi1 = (const float*)d_in[10];
    const float* Wi2 = (const float*)d_in[11];
    // d_in[12] = bi2: only shifts U, not dU/dr -> unused
    float* out = (float*)d_out;

    main_kernel<<<NFORCE + NMLP, 128>>>(t, z, lnw, W1, b1, Wv, bv, Wg, bg,
                                        Wi1, bi1, Wi2, out);
    reduce_kernel<<<(NN * 3) / 32, 256>>>(out);
}